// round 16
// baseline (speedup 1.0000x reference)
#include <cuda_runtime.h>
#include <cuda_fp16.h>
#include <cstdint>

#define HH   16
#define DH   64
#define DD   1024
#define SMAX 4096

// fp16 scratch (allocation-free rule: __device__ globals).
__device__ __half g_xqh[SMAX * DD], g_xql[SMAX * DD];
__device__ __half g_xkh[SMAX * DD], g_xkl[SMAX * DD];
__device__ __half g_xvh[SMAX * DD], g_xvl[SMAX * DD];
__device__ __half g_wqh[DD * DD], g_wkh[DD * DD], g_wvh[DD * DD], g_woh[DD * DD];
__device__ __half g_qh[HH * SMAX * DH], g_ql[HH * SMAX * DH];
__device__ __half g_kh[HH * SMAX * DH], g_vh[HH * SMAX * DH];
__device__ __half g_ch[HH * SMAX * DH], g_cl[HH * SMAX * DH];

// ===========================================================================
// Primitives
// ===========================================================================
__device__ __forceinline__ uint32_t smem_u32(const void* p) {
    uint32_t a;
    asm("{ .reg .u64 t; cvta.to.shared.u64 t, %1; cvt.u32.u64 %0, t; }"
        : "=r"(a) : "l"(p));
    return a;
}

#define LDSM_X4(r0, r1, r2, r3, addr)                                        \
    asm volatile("ldmatrix.sync.aligned.m8n8.x4.shared.b16 {%0,%1,%2,%3}, [%4];" \
                 : "=r"(r0), "=r"(r1), "=r"(r2), "=r"(r3) : "r"(addr))

#define LDSM_X4_T(r0, r1, r2, r3, addr)                                      \
    asm volatile("ldmatrix.sync.aligned.m8n8.x4.trans.shared.b16 {%0,%1,%2,%3}, [%4];" \
                 : "=r"(r0), "=r"(r1), "=r"(r2), "=r"(r3) : "r"(addr))

#define MMA16816(d, a, b0, b1)                                               \
    asm volatile("mma.sync.aligned.m16n8k16.row.col.f32.f16.f16.f32 "      \
                 "{%0,%1,%2,%3}, {%4,%5,%6,%7}, {%8,%9}, {%0,%1,%2,%3};"    \
                 : "+f"((d)[0]), "+f"((d)[1]), "+f"((d)[2]), "+f"((d)[3])    \
                 : "r"((a)[0]), "r"((a)[1]), "r"((a)[2]), "r"((a)[3]),       \
                   "r"(b0), "r"(b1))

#define CP16(dst, src)                                                       \
    asm volatile("cp.async.cg.shared.global [%0], [%1], 16;"                 \
                 :: "r"(dst), "l"(src) : "memory")
#define CP_COMMIT() asm volatile("cp.async.commit_group;" ::: "memory")
#define CP_WAIT0()  asm volatile("cp.async.wait_group 0;" ::: "memory")
#define CP_WAIT2()  asm volatile("cp.async.wait_group 2;" ::: "memory")

__device__ __forceinline__ void split_f16x2(float4 v, uint2& hv, uint2& lv) {
    __half2 h0 = __floats2half2_rn(v.x, v.y);
    __half2 h1 = __floats2half2_rn(v.z, v.w);
    __half2 l0 = __floats2half2_rn(v.x - __low2float(h0), v.y - __high2float(h0));
    __half2 l1 = __floats2half2_rn(v.z - __low2float(h1), v.w - __high2float(h1));
    hv = make_uint2(*reinterpret_cast<uint32_t*>(&h0),
                    *reinterpret_cast<uint32_t*>(&h1));
    lv = make_uint2(*reinterpret_cast<uint32_t*>(&l0),
                    *reinterpret_cast<uint32_t*>(&l1));
}

// ===========================================================================
// Pre-pass: fp32 -> fp16 hi/lo (X) and hi (W)
// ===========================================================================
__global__ __launch_bounds__(256) void cvt_x(
    const float* __restrict__ x0, const float* __restrict__ x1,
    const float* __restrict__ x2,
    __half* __restrict__ h0, __half* __restrict__ l0,
    __half* __restrict__ h1, __half* __restrict__ l1,
    __half* __restrict__ h2, __half* __restrict__ l2, int n4)
{
    const float* s; __half* hd; __half* ld;
    if (blockIdx.y == 0)      { s = x0; hd = h0; ld = l0; }
    else if (blockIdx.y == 1) { s = x1; hd = h1; ld = l1; }
    else                      { s = x2; hd = h2; ld = l2; }
    int idx = blockIdx.x * 256 + threadIdx.x;
    if (idx < n4) {
        float4 v = ((const float4*)s)[idx];
        uint2 hv, lv;
        split_f16x2(v, hv, lv);
        ((uint2*)hd)[idx] = hv;
        ((uint2*)ld)[idx] = lv;
    }
}

__global__ __launch_bounds__(256) void cvt_w(
    const float* __restrict__ w0, const float* __restrict__ w1,
    const float* __restrict__ w2, const float* __restrict__ w3,
    __half* __restrict__ o0, __half* __restrict__ o1,
    __half* __restrict__ o2, __half* __restrict__ o3, int n4)
{
    const float* s; __half* d;
    if (blockIdx.y == 0)      { s = w0; d = o0; }
    else if (blockIdx.y == 1) { s = w1; d = o1; }
    else if (blockIdx.y == 2) { s = w2; d = o2; }
    else                      { s = w3; d = o3; }
    int idx = blockIdx.x * 256 + threadIdx.x;
    if (idx < n4) {
        float4 v = ((const float4*)s)[idx];
        __half2 a = __floats2half2_rn(v.x, v.y);
        __half2 b = __floats2half2_rn(v.z, v.w);
        ((uint2*)d)[idx] = make_uint2(*reinterpret_cast<uint32_t*>(&a),
                                      *reinterpret_cast<uint32_t*>(&b));
    }
}

// ===========================================================================
// fp16x2 GEMM core (NT): C = (Ah+Al)*Bh^T + bias. cp.async 4-stage pipeline,
// one __syncthreads per BK=32 chunk. 128x128 CTA tile, 8 warps, 64x32 each.
// A_HM: A head-major [k>>6][m][k&63].  OUT_F: fp32 row-major out, else
// fp16 hi(+lo) head-major out.
// ===========================================================================
#define RS     40
#define TILE_E (128 * RS)            // elems per 128x32 tile
#define GB_E   (3 * TILE_E)          // elems per stage (Ah, Al, Bh)
#define GEMM_SMEM (4 * GB_E * 2)     // 122880 B

template<int A_HM, int OUT_F>
__device__ __forceinline__ void gemm_core(
    const __half* __restrict__ Agh, const __half* __restrict__ Agl,
    const __half* __restrict__ Bgh, const float* __restrict__ bias,
    __half* __restrict__ Chi, __half* __restrict__ Clo,
    float* __restrict__ Cf, int N, int Kd, int S)
{
    extern __shared__ __half gsm[];
    const uint32_t sb = smem_u32(gsm);

    const int t    = threadIdx.x;
    const int lane = t & 31, wid = t >> 5;
    const int wm   = wid >> 2;
    const int wn   = wid & 3;
    const int m0   = blockIdx.y << 7, n0 = blockIdx.x << 7;

    const int a_r  = wm * 64 + (lane & 15);
    const int a_c  = (lane >> 4) << 3;
    const int b_g  = lane >> 3;
    const int b_r  = wn * 32 + ((b_g >> 1) << 3) + (lane & 7);
    const int b_c  = (b_g & 1) << 3;

    float acc[4][4][4];
    #pragma unroll
    for (int i = 0; i < 4; i++)
        #pragma unroll
        for (int j = 0; j < 4; j++)
            #pragma unroll
            for (int r = 0; r < 4; r++) acc[i][j][r] = 0.0f;

    const int nch = Kd >> 5;   // 32

    // stage chunk k0 into ring stage p (6 cp.async per thread)
    auto stage = [&](int k0, int p) {
        const uint32_t db = sb + (uint32_t)p * (GB_E * 2);
        #pragma unroll
        for (int u = 0; u < 2; u++) {
            int gid = t + u * 256;          // 0..511
            int row = gid >> 2, cg = gid & 3;
            uint32_t d = db + row * 80 + cg * 16;
            size_t aoff;
            if (A_HM)
                aoff = ((size_t)(k0 >> 6) * S + m0 + row) * DH + (k0 & 63) + cg * 8;
            else
                aoff = (size_t)(m0 + row) * Kd + k0 + cg * 8;
            size_t boff = (size_t)(n0 + row) * Kd + k0 + cg * 8;
            CP16(d,                Agh + aoff);
            CP16(d + TILE_E * 2,   Agl + aoff);
            CP16(d + 2 * TILE_E * 2, Bgh + boff);
        }
    };

    stage(0, 0);  CP_COMMIT();
    stage(32, 1); CP_COMMIT();

    for (int i = 0; i < nch; i++) {
        if (i + 2 < nch) stage((i + 2) << 5, (i + 2) & 3);
        CP_COMMIT();                 // empty group at tail keeps count uniform
        CP_WAIT2();
        __syncthreads();

        const uint32_t base = sb + (uint32_t)(i & 3) * (GB_E * 2);
        const uint32_t AH = base, AL = base + TILE_E * 2, BH = base + 2 * TILE_E * 2;

        #pragma unroll
        for (int ks = 0; ks < 2; ks++) {
            const uint32_t acol = (a_c + (ks << 4)) << 1;
            const uint32_t bcol = (b_c + (ks << 4)) << 1;

            uint32_t aH[4][4], aL[4][4], bh[2][4];
            #pragma unroll
            for (int mf = 0; mf < 4; mf++) {
                uint32_t ra = (uint32_t)(a_r + mf * 16) * (RS * 2);
                LDSM_X4(aH[mf][0], aH[mf][1], aH[mf][2], aH[mf][3], AH + ra + acol);
            }
            #pragma unroll
            for (int ng = 0; ng < 2; ng++) {
                uint32_t rb = (uint32_t)(b_r + ng * 16) * (RS * 2);
                LDSM_X4(bh[ng][0], bh[ng][1], bh[ng][2], bh[ng][3], BH + rb + bcol);
            }
            #pragma unroll
            for (int mf = 0; mf < 4; mf++)
                #pragma unroll
                for (int nf = 0; nf < 4; nf++) {
                    const uint32_t* b = bh[nf >> 1] + ((nf & 1) << 1);
                    MMA16816(acc[mf][nf], aH[mf], b[0], b[1]);
                }
            #pragma unroll
            for (int mf = 0; mf < 4; mf++) {
                uint32_t ra = (uint32_t)(a_r + mf * 16) * (RS * 2);
                LDSM_X4(aL[mf][0], aL[mf][1], aL[mf][2], aL[mf][3], AL + ra + acol);
            }
            #pragma unroll
            for (int mf = 0; mf < 4; mf++)
                #pragma unroll
                for (int nf = 0; nf < 4; nf++) {
                    const uint32_t* b = bh[nf >> 1] + ((nf & 1) << 1);
                    MMA16816(acc[mf][nf], aL[mf], b[0], b[1]);
                }
        }
    }

    const int er = lane >> 2;
    const int ec = (lane & 3) << 1;
    #pragma unroll
    for (int mf = 0; mf < 4; mf++) {
        #pragma unroll
        for (int nf = 0; nf < 4; nf++) {
            int col  = n0 + wn * 32 + nf * 8 + ec;
            float bx = bias[col], by = bias[col + 1];
            int r0 = m0 + wm * 64 + mf * 16 + er;
            int r1 = r0 + 8;
            float v00 = acc[mf][nf][0] + bx, v01 = acc[mf][nf][1] + by;
            float v10 = acc[mf][nf][2] + bx, v11 = acc[mf][nf][3] + by;
            if (OUT_F) {
                *(float2*)(Cf + (size_t)r0 * N + col) = make_float2(v00, v01);
                *(float2*)(Cf + (size_t)r1 * N + col) = make_float2(v10, v11);
            } else {
                size_t base = (size_t)(col >> 6) * S;
                size_t i0 = (base + r0) * DH + (col & 63);
                size_t i1 = (base + r1) * DH + (col & 63);
                __half2 h0 = __floats2half2_rn(v00, v01);
                __half2 h1 = __floats2half2_rn(v10, v11);
                *(__half2*)(Chi + i0) = h0;
                *(__half2*)(Chi + i1) = h1;
                if (Clo) {
                    __half2 l0 = __floats2half2_rn(v00 - __low2float(h0),
                                                   v01 - __high2float(h0));
                    __half2 l1 = __floats2half2_rn(v10 - __low2float(h1),
                                                   v11 - __high2float(h1));
                    *(__half2*)(Clo + i0) = l0;
                    *(__half2*)(Clo + i1) = l1;
                }
            }
        }
    }
}

__global__ __launch_bounds__(256) void gemm_qkv(
    const __half* __restrict__ xqh, const __half* __restrict__ xql,
    const __half* __restrict__ xkh, const __half* __restrict__ xkl,
    const __half* __restrict__ xvh, const __half* __restrict__ xvl,
    const __half* __restrict__ wq, const __half* __restrict__ wk,
    const __half* __restrict__ wv,
    const float* __restrict__ bq, const float* __restrict__ bk,
    const float* __restrict__ bv,
    __half* __restrict__ qh, __half* __restrict__ ql,
    __half* __restrict__ kh, __half* __restrict__ vh, int S)
{
    const __half *Ah, *Al, *B;
    const float* bias;
    __half *Chi, *Clo;
    if (blockIdx.z == 0)      { Ah = xqh; Al = xql; B = wq; bias = bq; Chi = qh; Clo = ql; }
    else if (blockIdx.z == 1) { Ah = xkh; Al = xkl; B = wk; bias = bk; Chi = kh; Clo = nullptr; }
    else                      { Ah = xvh; Al = xvl; B = wv; bias = bv; Chi = vh; Clo = nullptr; }
    gemm_core<0, 0>(Ah, Al, B, bias, Chi, Clo, nullptr, DD, DD, S);
}

__global__ __launch_bounds__(256) void gemm_out(
    const __half* __restrict__ ch, const __half* __restrict__ cl,
    const __half* __restrict__ wo, const float* __restrict__ bo,
    float* __restrict__ out, int S)
{
    gemm_core<1, 1>(ch, cl, wo, bo, nullptr, nullptr, out, DD, DD, S);
}

// ===========================================================================
// Causal flash attention (fp16x2), cp.async 4-stage K/V ring, 1 sync/tile.
// One CTA = (head, 128 q rows), 8 warps, warp w owns rows [w*16, w*16+16).
// Q hi/lo in registers; K,V hi-only fp16 (pre-rounded by gemm_qkv epilogue).
// ===========================================================================
#define ARS    72
#define KVB_E  9216                  // elems per stage (Kh 4608 + Vh 4608)
#define VHo    4608
#define ATTN_SMEM (4 * KVB_E * 2)    // 73728 B

__global__ __launch_bounds__(256) void attn_mma(
    const __half* __restrict__ Qhg, const __half* __restrict__ Qlg,
    const __half* __restrict__ Khg, const __half* __restrict__ Vhg,
    __half* __restrict__ Ch, __half* __restrict__ Cl, int S)
{
    extern __shared__ __half sh[];
    const uint32_t sb = smem_u32(sh);

    const int hd = blockIdx.y;
    const int bq = gridDim.x - 1 - blockIdx.x;   // longest CTAs first
    const int i0 = bq << 7;
    const __half* Qh = Qhg + (size_t)hd * S * DH;
    const __half* Ql = Qlg + (size_t)hd * S * DH;
    const __half* Kh = Khg + (size_t)hd * S * DH;
    const __half* Vh = Vhg + (size_t)hd * S * DH;

    const int t = threadIdx.x, lane = t & 31, w = t >> 5;

    // ---- Q staging via cp.async into stages 0-1 (freed after frag load) ----
    #pragma unroll
    for (int u = 0; u < 4; u++) {
        int gid = t + u * 256;               // 0..1023
        int row = gid >> 3, cg = gid & 7;
        uint32_t d = sb + row * 144 + cg * 16;
        size_t off = (size_t)(i0 + row) * DH + cg * 8;
        CP16(d,         Qh + off);
        CP16(d + 18432, Ql + off);
    }
    CP_COMMIT();
    CP_WAIT0();
    __syncthreads();

    uint32_t qhi[4][4], qlo[4][4];
    {
        const uint32_t ar = (uint32_t)(w * 16 + (lane & 15)) * (ARS * 2);
        const uint32_t ac = ((lane >> 4) << 3) * 2;
        #pragma unroll
        for (int ks = 0; ks < 4; ks++) {
            LDSM_X4(qhi[ks][0], qhi[ks][1], qhi[ks][2], qhi[ks][3],
                    sb + ar + ac + ks * 32);
            LDSM_X4(qlo[ks][0], qlo[ks][1], qlo[ks][2], qlo[ks][3],
                    sb + 18432 + ar + ac + ks * 32);
        }
    }
    __syncthreads();   // all warps consumed Q before K/V overwrites stages 0-1

    float oacc[8][4];
    #pragma unroll
    for (int nf = 0; nf < 8; nf++)
        #pragma unroll
        for (int e = 0; e < 4; e++) oacc[nf][e] = 0.0f;
    float m0 = -1e30f, m1 = -1e30f, l0 = 0.0f, l1 = 0.0f;

    const int g    = lane >> 3;
    const uint32_t kb_r = ((g >> 1) << 3) + (lane & 7);
    const uint32_t kb_c = ((g & 1) << 3) * 2;
    const uint32_t vb_r = ((g & 1) << 3) + (lane & 7);
    const uint32_t vb_c = ((g >> 1) << 3) * 2;

    const int row_lo  = w * 16 + (lane >> 2);
    const int n_tiles = 2 * (bq + 1);

    // stage K/V tile j0 into ring stage p (4 cp.async per thread)
    auto stage_kv = [&](int j0, int p) {
        const uint32_t db = sb + (uint32_t)p * (KVB_E * 2);
        #pragma unroll
        for (int u = 0; u < 2; u++) {
            int gid = t + u * 256;           // 0..511
            int row = gid >> 3, cg = gid & 7;
            uint32_t d = db + row * 144 + cg * 16;
            size_t off = (size_t)(j0 + row) * DH + cg * 8;
            CP16(d,        Kh + off);
            CP16(d + 9216, Vh + off);
        }
    };

    stage_kv(0, 0);  CP_COMMIT();
    if (n_tiles > 1) stage_kv(64, 1);
    CP_COMMIT();

    for (int jt = 0; jt < n_tiles; jt++) {
        const int j0 = jt << 6;
        if (jt + 2 < n_tiles) stage_kv((jt + 2) << 6, (jt + 2) & 3);
        CP_COMMIT();
        CP_WAIT2();
        __syncthreads();

        if (j0 > i0 + w * 16 + 15) continue;   // fully-masked for this warp

        const uint32_t bo = (uint32_t)(jt & 3) * (KVB_E * 2);

        // ---- S = Q K^T (2 passes) ----
        float sacc[8][4];
        #pragma unroll
        for (int nf = 0; nf < 8; nf++)
            #pragma unroll
            for (int e = 0; e < 4; e++) sacc[nf][e] = 0.0f;

        #pragma unroll
        for (int ks = 0; ks < 4; ks++) {
            uint32_t kb[4][4];
            #pragma unroll
            for (int kg = 0; kg < 4; kg++)
                LDSM_X4(kb[kg][0], kb[kg][1], kb[kg][2], kb[kg][3],
                        sb + bo + (kg * 16 + kb_r) * (ARS * 2) + ks * 32 + kb_c);
            #pragma unroll
            for (int nf = 0; nf < 8; nf++) {
                const uint32_t* b = kb[nf >> 1] + ((nf & 1) << 1);
                MMA16816(sacc[nf], qhi[ks], b[0], b[1]);
            }
            #pragma unroll
            for (int nf = 0; nf < 8; nf++) {
                const uint32_t* b = kb[nf >> 1] + ((nf & 1) << 1);
                MMA16816(sacc[nf], qlo[ks], b[0], b[1]);
            }
        }

        // ---- softmax update ----
        const bool needmask = (j0 + 63 > i0 + w * 16);
        #pragma unroll
        for (int nf = 0; nf < 8; nf++) {
            #pragma unroll
            for (int e = 0; e < 4; e++) {
                float v = sacc[nf][e] * 0.125f;
                if (needmask) {
                    int col = j0 + nf * 8 + ((lane & 3) << 1) + (e & 1);
                    int row = i0 + row_lo + ((e >> 1) << 3);
                    if (col > row) v = -1e30f;
                }
                sacc[nf][e] = v;
            }
        }
        float mt0 = -1e30f, mt1 = -1e30f;
        #pragma unroll
        for (int nf = 0; nf < 8; nf++) {
            mt0 = fmaxf(mt0, fmaxf(sacc[nf][0], sacc[nf][1]));
            mt1 = fmaxf(mt1, fmaxf(sacc[nf][2], sacc[nf][3]));
        }
        mt0 = fmaxf(mt0, __shfl_xor_sync(0xffffffffu, mt0, 1));
        mt0 = fmaxf(mt0, __shfl_xor_sync(0xffffffffu, mt0, 2));
        mt1 = fmaxf(mt1, __shfl_xor_sync(0xffffffffu, mt1, 1));
        mt1 = fmaxf(mt1, __shfl_xor_sync(0xffffffffu, mt1, 2));

        float mn0 = fmaxf(m0, mt0), mn1 = fmaxf(m1, mt1);
        float a0 = __expf(m0 - mn0), a1 = __expf(m1 - mn1);
        m0 = mn0; m1 = mn1;

        float s0 = 0.0f, s1 = 0.0f;
        #pragma unroll
        for (int nf = 0; nf < 8; nf++) {
            sacc[nf][0] = __expf(sacc[nf][0] - m0);
            sacc[nf][1] = __expf(sacc[nf][1] - m0);
            sacc[nf][2] = __expf(sacc[nf][2] - m1);
            sacc[nf][3] = __expf(sacc[nf][3] - m1);
            s0 += sacc[nf][0] + sacc[nf][1];
            s1 += sacc[nf][2] + sacc[nf][3];
        }
        s0 += __shfl_xor_sync(0xffffffffu, s0, 1);
        s0 += __shfl_xor_sync(0xffffffffu, s0, 2);
        s1 += __shfl_xor_sync(0xffffffffu, s1, 1);
        s1 += __shfl_xor_sync(0xffffffffu, s1, 2);
        l0 = l0 * a0 + s0;
        l1 = l1 * a1 + s1;
        #pragma unroll
        for (int nf = 0; nf < 8; nf++) {
            oacc[nf][0] *= a0; oacc[nf][1] *= a0;
            oacc[nf][2] *= a1; oacc[nf][3] *= a1;
        }

        // ---- O += P V (P hi/lo built in registers) ----
        #pragma unroll
        for (int ks = 0; ks < 4; ks++) {
            uint32_t phi[4], plo[4];
            #pragma unroll
            for (int half = 0; half < 2; half++) {
                const float* p = sacc[2 * ks + half];
                __half2 h01 = __floats2half2_rn(p[0], p[1]);
                __half2 h23 = __floats2half2_rn(p[2], p[3]);
                __half2 l01 = __floats2half2_rn(
                    p[0] - __low2float(h01), p[1] - __high2float(h01));
                __half2 l23 = __floats2half2_rn(
                    p[2] - __low2float(h23), p[3] - __high2float(h23));
                phi[half * 2 + 0] = *reinterpret_cast<uint32_t*>(&h01);
                phi[half * 2 + 1] = *reinterpret_cast<uint32_t*>(&h23);
                plo[half * 2 + 0] = *reinterpret_cast<uint32_t*>(&l01);
                plo[half * 2 + 1] = *reinterpret_cast<uint32_t*>(&l23);
            }
            uint32_t vb[4][4];
            #pragma unroll
            for (int kg = 0; kg < 4; kg++)
                LDSM_X4_T(vb[kg][0], vb[kg][1], vb[kg][2], vb[kg][3],
                          sb + bo + VHo * 2 + (ks * 16 + vb_r) * (ARS * 2) + kg * 32 + vb_c);
            #pragma unroll
            for (int nf = 0; nf < 8; nf++) {
                const uint32_t* b = vb[nf >> 1] + ((nf & 1) << 1);
                MMA16816(oacc[nf], phi, b[0], b[1]);
            }
            #pragma unroll
            for (int nf = 0; nf < 8; nf++) {
                const uint32_t* b = vb[nf >> 1] + ((nf & 1) << 1);
                MMA16816(oacc[nf], plo, b[0], b[1]);
            }
        }
    }

    // ---- normalize + store ctx as fp16 hi/lo ----
    const float inv0 = 1.0f / l0, inv1 = 1.0f / l1;
    const int r0 = i0 + row_lo;
    #pragma unroll
    for (int nf = 0; nf < 8; nf++) {
        int col = nf * 8 + ((lane & 3) << 1);
        float v00 = oacc[nf][0] * inv0, v01 = oacc[nf][1] * inv0;
        float v10 = oacc[nf][2] * inv1, v11 = oacc[nf][3] * inv1;
        size_t i0e = ((size_t)hd * S + r0) * DH + col;
        size_t i1e = ((size_t)hd * S + r0 + 8) * DH + col;
        __half2 h0 = __floats2half2_rn(v00, v01);
        __half2 h1 = __floats2half2_rn(v10, v11);
        __half2 lo0 = __floats2half2_rn(v00 - __low2float(h0), v01 - __high2float(h0));
        __half2 lo1 = __floats2half2_rn(v10 - __low2float(h1), v11 - __high2float(h1));
        *(__half2*)(Ch + i0e) = h0;
        *(__half2*)(Cl + i0e) = lo0;
        *(__half2*)(Ch + i1e) = h1;
        *(__half2*)(Cl + i1e) = lo1;
    }
}

// ---------------------------------------------------------------------------
extern "C" void kernel_launch(void* const* d_in, const int* in_sizes, int n_in,
                              void* d_out, int out_size)
{
    const float* Xq = (const float*)d_in[0];
    const float* Xk = (const float*)d_in[1];
    const float* Xv = (const float*)d_in[2];
    const float* Wq = (const float*)d_in[3];
    const float* bq = (const float*)d_in[4];
    const float* Wk = (const float*)d_in[5];
    const float* bk = (const float*)d_in[6];
    const float* Wv = (const float*)d_in[7];
    const float* bv = (const float*)d_in[8];
    const float* Wo = (const float*)d_in[9];
    const float* bo = (const float*)d_in[10];
    float* out = (float*)d_out;

    const int S = in_sizes[0] / DD;   // 4096

    __half *xqh, *xql, *xkh, *xkl, *xvh, *xvl;
    __half *wqh, *wkh, *wvh, *woh;
    __half *qh, *ql, *kh, *vh, *ch, *cl;
    cudaGetSymbolAddress((void**)&xqh, g_xqh); cudaGetSymbolAddress((void**)&xql, g_xql);
    cudaGetSymbolAddress((void**)&xkh, g_xkh); cudaGetSymbolAddress((void**)&xkl, g_xkl);
    cudaGetSymbolAddress((void**)&xvh, g_xvh); cudaGetSymbolAddress((void**)&xvl, g_xvl);
    cudaGetSymbolAddress((void**)&wqh, g_wqh); cudaGetSymbolAddress((void**)&wkh, g_wkh);
    cudaGetSymbolAddress((void**)&wvh, g_wvh); cudaGetSymbolAddress((void**)&woh, g_woh);
    cudaGetSymbolAddress((void**)&qh, g_qh);   cudaGetSymbolAddress((void**)&ql, g_ql);
    cudaGetSymbolAddress((void**)&kh, g_kh);   cudaGetSymbolAddress((void**)&vh, g_vh);
    cudaGetSymbolAddress((void**)&ch, g_ch);   cudaGetSymbolAddress((void**)&cl, g_cl);

    cudaFuncSetAttribute(gemm_qkv,
                         cudaFuncAttributeMaxDynamicSharedMemorySize, GEMM_SMEM);
    cudaFuncSetAttribute(gemm_out,
                         cudaFuncAttributeMaxDynamicSharedMemorySize, GEMM_SMEM);
    cudaFuncSetAttribute(attn_mma,
                         cudaFuncAttributeMaxDynamicSharedMemorySize, ATTN_SMEM);

    const int n4x = S * DD / 4;       // 1M
    const int n4w = DD * DD / 4;      // 256K
    cvt_x<<<dim3((n4x + 255) / 256, 3), 256>>>(Xq, Xk, Xv,
                                               xqh, xql, xkh, xkl, xvh, xvl, n4x);
    cvt_w<<<dim3((n4w + 255) / 256, 4), 256>>>(Wq, Wk, Wv, Wo,
                                               wqh, wkh, wvh, woh, n4w);

    gemm_qkv<<<dim3(DD / 128, S / 128, 3), 256, GEMM_SMEM>>>(
        xqh, xql, xkh, xkl, xvh, xvl, wqh, wkh, wvh, bq, bk, bv,
        qh, ql, kh, vh, S);

    attn_mma<<<dim3(S / 128, HH), 256, ATTN_SMEM>>>(qh, ql, kh, vh, ch, cl, S);

    gemm_out<<<dim3(DD / 128, S / 128), 256, GEMM_SMEM>>>(ch, cl, woh, bo, out, S);
}

// round 17
// speedup vs baseline: 1.0658x; 1.0658x over previous
#include <cuda_runtime.h>
#include <cuda_fp16.h>
#include <cstdint>

#define HH   16
#define DH   64
#define DD   1024
#define SMAX 4096

// Scratch (allocation-free rule: __device__ globals).
__device__ float  g_q[HH * SMAX * DH];
__device__ float  g_k[HH * SMAX * DH];
__device__ float  g_v[HH * SMAX * DH];
__device__ __half g_xqh[SMAX * DD], g_xql[SMAX * DD];
__device__ __half g_xkh[SMAX * DD], g_xkl[SMAX * DD];
__device__ __half g_xvh[SMAX * DD], g_xvl[SMAX * DD];
__device__ __half g_wqh[DD * DD], g_wkh[DD * DD], g_wvh[DD * DD], g_woh[DD * DD];
__device__ __half g_ch[HH * SMAX * DH], g_cl[HH * SMAX * DH];

// ===========================================================================
// Primitives
// ===========================================================================
__device__ __forceinline__ uint32_t smem_u32(const void* p) {
    uint32_t a;
    asm("{ .reg .u64 t; cvta.to.shared.u64 t, %1; cvt.u32.u64 %0, t; }"
        : "=r"(a) : "l"(p));
    return a;
}

#define LDSM_X4(r0, r1, r2, r3, addr)                                        \
    asm volatile("ldmatrix.sync.aligned.m8n8.x4.shared.b16 {%0,%1,%2,%3}, [%4];" \
                 : "=r"(r0), "=r"(r1), "=r"(r2), "=r"(r3) : "r"(addr))

#define LDSM_X4_T(r0, r1, r2, r3, addr)                                      \
    asm volatile("ldmatrix.sync.aligned.m8n8.x4.trans.shared.b16 {%0,%1,%2,%3}, [%4];" \
                 : "=r"(r0), "=r"(r1), "=r"(r2), "=r"(r3) : "r"(addr))

#define MMA16816(d, a, b0, b1)                                               \
    asm volatile("mma.sync.aligned.m16n8k16.row.col.f32.f16.f16.f32 "      \
                 "{%0,%1,%2,%3}, {%4,%5,%6,%7}, {%8,%9}, {%0,%1,%2,%3};"    \
                 : "+f"((d)[0]), "+f"((d)[1]), "+f"((d)[2]), "+f"((d)[3])    \
                 : "r"((a)[0]), "r"((a)[1]), "r"((a)[2]), "r"((a)[3]),       \
                   "r"(b0), "r"(b1))

#define CP16(dst, src)                                                       \
    asm volatile("cp.async.cg.shared.global [%0], [%1], 16;"                 \
                 :: "r"(dst), "l"(src) : "memory")
#define CP_COMMIT() asm volatile("cp.async.commit_group;" ::: "memory")
#define CP_WAIT0()  asm volatile("cp.async.wait_group 0;" ::: "memory")

// fp16 hi conversion only
__device__ __forceinline__ uint2 cvt_f16(float4 v) {
    __half2 h0 = __floats2half2_rn(v.x, v.y);
    __half2 h1 = __floats2half2_rn(v.z, v.w);
    return make_uint2(*reinterpret_cast<uint32_t*>(&h0),
                      *reinterpret_cast<uint32_t*>(&h1));
}

__device__ __forceinline__ void split_f16x2(float4 v, uint2& hv, uint2& lv) {
    __half2 h0 = __floats2half2_rn(v.x, v.y);
    __half2 h1 = __floats2half2_rn(v.z, v.w);
    __half2 l0 = __floats2half2_rn(v.x - __low2float(h0), v.y - __high2float(h0));
    __half2 l1 = __floats2half2_rn(v.z - __low2float(h1), v.w - __high2float(h1));
    hv = make_uint2(*reinterpret_cast<uint32_t*>(&h0),
                    *reinterpret_cast<uint32_t*>(&h1));
    lv = make_uint2(*reinterpret_cast<uint32_t*>(&l0),
                    *reinterpret_cast<uint32_t*>(&l1));
}

// ===========================================================================
// Pre-pass: fp32 -> fp16 hi/lo (X) and hi (W). Same rounding as R15 in-kernel.
// ===========================================================================
__global__ __launch_bounds__(256) void cvt_x(
    const float* __restrict__ x0, const float* __restrict__ x1,
    const float* __restrict__ x2,
    __half* __restrict__ h0, __half* __restrict__ l0,
    __half* __restrict__ h1, __half* __restrict__ l1,
    __half* __restrict__ h2, __half* __restrict__ l2, int n4)
{
    const float* s; __half* hd; __half* ld;
    if (blockIdx.y == 0)      { s = x0; hd = h0; ld = l0; }
    else if (blockIdx.y == 1) { s = x1; hd = h1; ld = l1; }
    else                      { s = x2; hd = h2; ld = l2; }
    int idx = blockIdx.x * 256 + threadIdx.x;
    if (idx < n4) {
        float4 v = ((const float4*)s)[idx];
        uint2 hv, lv;
        split_f16x2(v, hv, lv);
        ((uint2*)hd)[idx] = hv;
        ((uint2*)ld)[idx] = lv;
    }
}

__global__ __launch_bounds__(256) void cvt_w(
    const float* __restrict__ w0, const float* __restrict__ w1,
    const float* __restrict__ w2, const float* __restrict__ w3,
    __half* __restrict__ o0, __half* __restrict__ o1,
    __half* __restrict__ o2, __half* __restrict__ o3, int n4)
{
    const float* s; __half* d;
    if (blockIdx.y == 0)      { s = w0; d = o0; }
    else if (blockIdx.y == 1) { s = w1; d = o1; }
    else if (blockIdx.y == 2) { s = w2; d = o2; }
    else                      { s = w3; d = o3; }
    int idx = blockIdx.x * 256 + threadIdx.x;
    if (idx < n4) {
        float4 v = ((const float4*)s)[idx];
        ((uint2*)d)[idx] = cvt_f16(v);
    }
}

// ===========================================================================
// fp16x2 GEMM (NT): C = (Ah+Al)*Bh^T + bias. cp.async 2-stage ring,
// ONE __syncthreads per BK=32 chunk, 2 CTAs/SM (61 KB smem, <=128 regs).
// A_HM: A head-major [k>>6][m][k&63]. C_HM: C fp32 head-major, else row-major.
// ===========================================================================
#define RS     40
#define TILE_E (128 * RS)            // 5120 elems per 128x32 fp16 tile
#define GST_E  (3 * TILE_E)          // stage: Ah, Al, Bh
#define GEMM_SMEM (2 * GST_E * 2)    // 61440 B

template<int A_HM, int C_HM>
__device__ __forceinline__ void gemm_core(
    const __half* __restrict__ Agh, const __half* __restrict__ Agl,
    const __half* __restrict__ Bgh, const float* __restrict__ bias,
    float* __restrict__ C, int N, int Kd, int S)
{
    extern __shared__ __half gsm[];
    const uint32_t sb = smem_u32(gsm);

    const int t    = threadIdx.x;
    const int lane = t & 31, wid = t >> 5;
    const int wm   = wid >> 2;
    const int wn   = wid & 3;
    const int m0   = blockIdx.y << 7, n0 = blockIdx.x << 7;

    const int a_r  = wm * 64 + (lane & 15);
    const int a_c  = (lane >> 4) << 3;
    const int b_g  = lane >> 3;
    const int b_r  = wn * 32 + ((b_g >> 1) << 3) + (lane & 7);
    const int b_c  = (b_g & 1) << 3;

    float acc[4][4][4];
    #pragma unroll
    for (int i = 0; i < 4; i++)
        #pragma unroll
        for (int j = 0; j < 4; j++)
            #pragma unroll
            for (int r = 0; r < 4; r++) acc[i][j][r] = 0.0f;

    const int nch = Kd >> 5;   // 32

    // stage chunk k0 into ring stage p (6 cp.async of 16 B per thread)
    auto stage = [&](int k0, int p) {
        const uint32_t db = sb + (uint32_t)p * (GST_E * 2);
        #pragma unroll
        for (int u = 0; u < 2; u++) {
            int gid = t + u * 256;          // 0..511
            int row = gid >> 2, cg = gid & 3;
            uint32_t d = db + row * 80 + cg * 16;
            size_t aoff;
            if (A_HM)
                aoff = ((size_t)(k0 >> 6) * S + m0 + row) * DH + (k0 & 63) + cg * 8;
            else
                aoff = (size_t)(m0 + row) * Kd + k0 + cg * 8;
            size_t boff = (size_t)(n0 + row) * Kd + k0 + cg * 8;
            CP16(d,                  Agh + aoff);
            CP16(d + TILE_E * 2,     Agl + aoff);
            CP16(d + 2 * TILE_E * 2, Bgh + boff);
        }
    };

    stage(0, 0);
    CP_COMMIT();

    for (int i = 0; i < nch; i++) {
        CP_WAIT0();          // own stage(i) copies landed
        __syncthreads();     // all threads landed; prev MMA reads done

        if (i + 1 < nch) {   // fill the other buffer under this chunk's MMA
            stage((i + 1) << 5, (i + 1) & 1);
            CP_COMMIT();
        }

        const uint32_t base = sb + (uint32_t)(i & 1) * (GST_E * 2);
        const uint32_t AH = base, AL = base + TILE_E * 2, BH = base + 2 * TILE_E * 2;

        #pragma unroll
        for (int ks = 0; ks < 2; ks++) {
            const uint32_t acol = (a_c + (ks << 4)) << 1;
            const uint32_t bcol = (b_c + (ks << 4)) << 1;

            uint32_t aH[4][4], aL[4][4], bh[2][4];
            #pragma unroll
            for (int mf = 0; mf < 4; mf++) {
                uint32_t ra = (uint32_t)(a_r + mf * 16) * (RS * 2);
                LDSM_X4(aH[mf][0], aH[mf][1], aH[mf][2], aH[mf][3], AH + ra + acol);
            }
            #pragma unroll
            for (int ng = 0; ng < 2; ng++) {
                uint32_t rb = (uint32_t)(b_r + ng * 16) * (RS * 2);
                LDSM_X4(bh[ng][0], bh[ng][1], bh[ng][2], bh[ng][3], BH + rb + bcol);
            }
            #pragma unroll
            for (int mf = 0; mf < 4; mf++)
                #pragma unroll
                for (int nf = 0; nf < 4; nf++) {
                    const uint32_t* b = bh[nf >> 1] + ((nf & 1) << 1);
                    MMA16816(acc[mf][nf], aH[mf], b[0], b[1]);
                }
            #pragma unroll
            for (int mf = 0; mf < 4; mf++) {
                uint32_t ra = (uint32_t)(a_r + mf * 16) * (RS * 2);
                LDSM_X4(aL[mf][0], aL[mf][1], aL[mf][2], aL[mf][3], AL + ra + acol);
            }
            #pragma unroll
            for (int mf = 0; mf < 4; mf++)
                #pragma unroll
                for (int nf = 0; nf < 4; nf++) {
                    const uint32_t* b = bh[nf >> 1] + ((nf & 1) << 1);
                    MMA16816(acc[mf][nf], aL[mf], b[0], b[1]);
                }
        }
    }

    const int er = lane >> 2;
    const int ec = (lane & 3) << 1;
    #pragma unroll
    for (int mf = 0; mf < 4; mf++) {
        #pragma unroll
        for (int nf = 0; nf < 4; nf++) {
            int col  = n0 + wn * 32 + nf * 8 + ec;
            float bx = bias[col], by = bias[col + 1];
            int r0 = m0 + wm * 64 + mf * 16 + er;
            int r1 = r0 + 8;
            float2 o0 = make_float2(acc[mf][nf][0] + bx, acc[mf][nf][1] + by);
            float2 o1 = make_float2(acc[mf][nf][2] + bx, acc[mf][nf][3] + by);
            if (C_HM) {
                size_t base = (size_t)(col >> 6) * S;
                *(float2*)(C + (base + r0) * DH + (col & 63)) = o0;
                *(float2*)(C + (base + r1) * DH + (col & 63)) = o1;
            } else {
                *(float2*)(C + (size_t)r0 * N + col) = o0;
                *(float2*)(C + (size_t)r1 * N + col) = o1;
            }
        }
    }
}

__global__ __launch_bounds__(256, 2) void gemm_qkv(
    const __half* __restrict__ xqh, const __half* __restrict__ xql,
    const __half* __restrict__ xkh, const __half* __restrict__ xkl,
    const __half* __restrict__ xvh, const __half* __restrict__ xvl,
    const __half* __restrict__ wq, const __half* __restrict__ wk,
    const __half* __restrict__ wv,
    const float* __restrict__ bq, const float* __restrict__ bk,
    const float* __restrict__ bv,
    float* __restrict__ q, float* __restrict__ k, float* __restrict__ v, int S)
{
    const __half *Ah, *Al, *B;
    const float* bias;
    float* C;
    if (blockIdx.z == 0)      { Ah = xqh; Al = xql; B = wq; bias = bq; C = q; }
    else if (blockIdx.z == 1) { Ah = xkh; Al = xkl; B = wk; bias = bk; C = k; }
    else                      { Ah = xvh; Al = xvl; B = wv; bias = bv; C = v; }
    gemm_core<0, 1>(Ah, Al, B, bias, C, DD, DD, S);
}

__global__ __launch_bounds__(256, 2) void gemm_out(
    const __half* __restrict__ ch, const __half* __restrict__ cl,
    const __half* __restrict__ wo, const float* __restrict__ bo,
    float* __restrict__ out, int S)
{
    gemm_core<1, 0>(ch, cl, wo, bo, out, DD, DD, S);
}

// ===========================================================================
// Causal flash attention (fp16x2) — R15 version verbatim; only the epilogue
// changed: ctx written as fp16 hi/lo (same rounding as a post-pass convert).
// ===========================================================================
#define ARS   72
#define BUFE  9216
#define KHo   0
#define VHo   4608
#define QLoO  9216
#define ATTN_SMEM (2 * BUFE * 2)   // 36864 bytes

__global__ __launch_bounds__(256) void attn_mma(
    const float* __restrict__ Q, const float* __restrict__ K,
    const float* __restrict__ V,
    __half* __restrict__ Ch, __half* __restrict__ Cl, int S)
{
    extern __shared__ __half sh[];
    const uint32_t sb = smem_u32(sh);

    const int hd = blockIdx.y;
    const int bq = gridDim.x - 1 - blockIdx.x;   // longest CTAs first
    const int i0 = bq << 7;
    const float* Qh = Q + (size_t)hd * S * DH;
    const float* Kh = K + (size_t)hd * S * DH;
    const float* Vh = V + (size_t)hd * S * DH;

    const int t = threadIdx.x, lane = t & 31, w = t >> 5;

    // ---- stage Q (128x64) as hi/lo fp16 ----
    #pragma unroll
    for (int u = 0; u < 8; u++) {
        int idx = t + u * 256;
        int row = idx >> 4;
        int c4  = (idx & 15) << 2;
        float4 qv = *(const float4*)(Qh + (size_t)(i0 + row) * DH + c4);
        uint2 hv, lv;
        split_f16x2(qv, hv, lv);
        *(uint2*)(sh + row * ARS + c4)        = hv;
        *(uint2*)(sh + QLoO + row * ARS + c4) = lv;
    }
    __syncthreads();

    uint32_t qhi[4][4], qlo[4][4];
    {
        const uint32_t ar = (uint32_t)(w * 16 + (lane & 15)) * (ARS * 2);
        const uint32_t ac = ((lane >> 4) << 3) * 2;
        #pragma unroll
        for (int ks = 0; ks < 4; ks++) {
            LDSM_X4(qhi[ks][0], qhi[ks][1], qhi[ks][2], qhi[ks][3],
                    sb + ar + ac + ks * 32);
            LDSM_X4(qlo[ks][0], qlo[ks][1], qlo[ks][2], qlo[ks][3],
                    sb + QLoO * 2 + ar + ac + ks * 32);
        }
    }

    float oacc[8][4];
    #pragma unroll
    for (int nf = 0; nf < 8; nf++)
        #pragma unroll
        for (int e = 0; e < 4; e++) oacc[nf][e] = 0.0f;
    float m0 = -1e30f, m1 = -1e30f, l0 = 0.0f, l1 = 0.0f;

    const int g    = lane >> 3;
    const uint32_t kb_r = ((g >> 1) << 3) + (lane & 7);
    const uint32_t kb_c = ((g & 1) << 3) * 2;
    const uint32_t vb_r = ((g & 1) << 3) + (lane & 7);
    const uint32_t vb_c = ((g >> 1) << 3) * 2;

    const int row_lo  = w * 16 + (lane >> 2);
    const int n_tiles = 2 * (bq + 1);

    const int lrow = t >> 4;
    const int lc4  = (t & 15) << 2;

    float4 kv4[4], vv4[4];
    #pragma unroll
    for (int u = 0; u < 4; u++) {
        int row = lrow + (u << 4);
        kv4[u] = *(const float4*)(Kh + (size_t)row * DH + lc4);
        vv4[u] = *(const float4*)(Vh + (size_t)row * DH + lc4);
    }
    __syncthreads();
    #pragma unroll
    for (int u = 0; u < 4; u++) {
        int row = lrow + (u << 4);
        *(uint2*)(sh + KHo + row * ARS + lc4) = cvt_f16(kv4[u]);
        *(uint2*)(sh + VHo + row * ARS + lc4) = cvt_f16(vv4[u]);
    }
    if (n_tiles > 1) {
        #pragma unroll
        for (int u = 0; u < 4; u++) {
            int row = 64 + lrow + (u << 4);
            kv4[u] = *(const float4*)(Kh + (size_t)row * DH + lc4);
            vv4[u] = *(const float4*)(Vh + (size_t)row * DH + lc4);
        }
    }
    __syncthreads();

    for (int jt = 0; jt < n_tiles; jt++) {
        const int j0   = jt << 6;
        const uint32_t bo = (uint32_t)(jt & 1) * (BUFE * 2);

        if (j0 <= i0 + w * 16 + 15) {
            // ---- S = Q K^T (2 passes) ----
            float sacc[8][4];
            #pragma unroll
            for (int nf = 0; nf < 8; nf++)
                #pragma unroll
                for (int e = 0; e < 4; e++) sacc[nf][e] = 0.0f;

            #pragma unroll
            for (int ks = 0; ks < 4; ks++) {
                uint32_t kb[4][4];
                #pragma unroll
                for (int kg = 0; kg < 4; kg++)
                    LDSM_X4(kb[kg][0], kb[kg][1], kb[kg][2], kb[kg][3],
                            sb + bo + KHo * 2 + (kg * 16 + kb_r) * (ARS * 2) + ks * 32 + kb_c);
                #pragma unroll
                for (int nf = 0; nf < 8; nf++) {
                    const uint32_t* b = kb[nf >> 1] + ((nf & 1) << 1);
                    MMA16816(sacc[nf], qhi[ks], b[0], b[1]);
                }
                #pragma unroll
                for (int nf = 0; nf < 8; nf++) {
                    const uint32_t* b = kb[nf >> 1] + ((nf & 1) << 1);
                    MMA16816(sacc[nf], qlo[ks], b[0], b[1]);
                }
            }

            // ---- softmax update ----
            const bool needmask = (j0 + 63 > i0 + w * 16);
            #pragma unroll
            for (int nf = 0; nf < 8; nf++) {
                #pragma unroll
                for (int e = 0; e < 4; e++) {
                    float v = sacc[nf][e] * 0.125f;
                    if (needmask) {
                        int col = j0 + nf * 8 + ((lane & 3) << 1) + (e & 1);
                        int row = i0 + row_lo + ((e >> 1) << 3);
                        if (col > row) v = -1e30f;
                    }
                    sacc[nf][e] = v;
                }
            }
            float mt0 = -1e30f, mt1 = -1e30f;
            #pragma unroll
            for (int nf = 0; nf < 8; nf++) {
                mt0 = fmaxf(mt0, fmaxf(sacc[nf][0], sacc[nf][1]));
                mt1 = fmaxf(mt1, fmaxf(sacc[nf][2], sacc[nf][3]));
            }
            mt0 = fmaxf(mt0, __shfl_xor_sync(0xffffffffu, mt0, 1));
            mt0 = fmaxf(mt0, __shfl_xor_sync(0xffffffffu, mt0, 2));
            mt1 = fmaxf(mt1, __shfl_xor_sync(0xffffffffu, mt1, 1));
            mt1 = fmaxf(mt1, __shfl_xor_sync(0xffffffffu, mt1, 2));

            float mn0 = fmaxf(m0, mt0), mn1 = fmaxf(m1, mt1);
            float a0 = __expf(m0 - mn0), a1 = __expf(m1 - mn1);
            m0 = mn0; m1 = mn1;

            float s0 = 0.0f, s1 = 0.0f;
            #pragma unroll
            for (int nf = 0; nf < 8; nf++) {
                sacc[nf][0] = __expf(sacc[nf][0] - m0);
                sacc[nf][1] = __expf(sacc[nf][1] - m0);
                sacc[nf][2] = __expf(sacc[nf][2] - m1);
                sacc[nf][3] = __expf(sacc[nf][3] - m1);
                s0 += sacc[nf][0] + sacc[nf][1];
                s1 += sacc[nf][2] + sacc[nf][3];
            }
            s0 += __shfl_xor_sync(0xffffffffu, s0, 1);
            s0 += __shfl_xor_sync(0xffffffffu, s0, 2);
            s1 += __shfl_xor_sync(0xffffffffu, s1, 1);
            s1 += __shfl_xor_sync(0xffffffffu, s1, 2);
            l0 = l0 * a0 + s0;
            l1 = l1 * a1 + s1;
            #pragma unroll
            for (int nf = 0; nf < 8; nf++) {
                oacc[nf][0] *= a0; oacc[nf][1] *= a0;
                oacc[nf][2] *= a1; oacc[nf][3] *= a1;
            }

            // ---- O += P V (P hi/lo built in registers) ----
            #pragma unroll
            for (int ks = 0; ks < 4; ks++) {
                uint32_t phi[4], plo[4];
                #pragma unroll
                for (int half = 0; half < 2; half++) {
                    const float* p = sacc[2 * ks + half];
                    __half2 h01 = __floats2half2_rn(p[0], p[1]);
                    __half2 h23 = __floats2half2_rn(p[2], p[3]);
                    __half2 l01 = __floats2half2_rn(
                        p[0] - __low2float(h01), p[1] - __high2float(h01));
                    __half2 l23 = __floats2half2_rn(
                        p[2] - __low2float(h23), p[3] - __high2float(h23));
                    phi[half * 2 + 0] = *reinterpret_cast<uint32_t*>(&h01);
                    phi[half * 2 + 1] = *reinterpret_cast<uint32_t*>(&h23);
                    plo[half * 2 + 0] = *reinterpret_cast<uint32_t*>(&l01);
                    plo[half * 2 + 1] = *reinterpret_cast<uint32_t*>(&l23);
                }
                uint32_t vb[4][4];
                #pragma unroll
                for (int kg = 0; kg < 4; kg++)
                    LDSM_X4_T(vb[kg][0], vb[kg][1], vb[kg][2], vb[kg][3],
                              sb + bo + VHo * 2 + (ks * 16 + vb_r) * (ARS * 2) + kg * 32 + vb_c);
                #pragma unroll
                for (int nf = 0; nf < 8; nf++) {
                    const uint32_t* b = vb[nf >> 1] + ((nf & 1) << 1);
                    MMA16816(oacc[nf], phi, b[0], b[1]);
                }
                #pragma unroll
                for (int nf = 0; nf < 8; nf++) {
                    const uint32_t* b = vb[nf >> 1] + ((nf & 1) << 1);
                    MMA16816(oacc[nf], plo, b[0], b[1]);
                }
            }
        }

        if (jt + 1 < n_tiles) {
            __half* dst = sh + ((jt + 1) & 1) * BUFE;
            #pragma unroll
            for (int u = 0; u < 4; u++) {
                int row = lrow + (u << 4);
                *(uint2*)(dst + KHo + row * ARS + lc4) = cvt_f16(kv4[u]);
                *(uint2*)(dst + VHo + row * ARS + lc4) = cvt_f16(vv4[u]);
            }
            if (jt + 2 < n_tiles) {
                const int jn = (jt + 2) << 6;
                #pragma unroll
                for (int u = 0; u < 4; u++) {
                    int row = jn + lrow + (u << 4);
                    kv4[u] = *(const float4*)(Kh + (size_t)row * DH + lc4);
                    vv4[u] = *(const float4*)(Vh + (size_t)row * DH + lc4);
                }
            }
        }
        __syncthreads();
    }

    // ---- normalize + store ctx as fp16 hi/lo ----
    const float inv0 = 1.0f / l0, inv1 = 1.0f / l1;
    const int r0 = i0 + row_lo;
    #pragma unroll
    for (int nf = 0; nf < 8; nf++) {
        int col = nf * 8 + ((lane & 3) << 1);
        float v00 = oacc[nf][0] * inv0, v01 = oacc[nf][1] * inv0;
        float v10 = oacc[nf][2] * inv1, v11 = oacc[nf][3] * inv1;
        size_t i0e = ((size_t)hd * S + r0) * DH + col;
        size_t i1e = ((size_t)hd * S + r0 + 8) * DH + col;
        __half2 h0 = __floats2half2_rn(v00, v01);
        __half2 h1 = __floats2half2_rn(v10, v11);
        __half2 lo0 = __floats2half2_rn(v00 - __low2float(h0), v01 - __high2float(h0));
        __half2 lo1 = __floats2half2_rn(v10 - __low2float(h1), v11 - __high2float(h1));
        *(__half2*)(Ch + i0e) = h0;
        *(__half2*)(Cl + i0e) = lo0;
        *(__half2*)(Ch + i1e) = h1;
        *(__half2*)(Cl + i1e) = lo1;
    }
}

// ---------------------------------------------------------------------------
extern "C" void kernel_launch(void* const* d_in, const int* in_sizes, int n_in,
                              void* d_out, int out_size)
{
    const float* Xq = (const float*)d_in[0];
    const float* Xk = (const float*)d_in[1];
    const float* Xv = (const float*)d_in[2];
    const float* Wq = (const float*)d_in[3];
    const float* bq = (const float*)d_in[4];
    const float* Wk = (const float*)d_in[5];
    const float* bk = (const float*)d_in[6];
    const float* Wv = (const float*)d_in[7];
    const float* bv = (const float*)d_in[8];
    const float* Wo = (const float*)d_in[9];
    const float* bo = (const float*)d_in[10];
    float* out = (float*)d_out;

    const int S = in_sizes[0] / DD;   // 4096

    float *q, *k, *v;
    __half *xqh, *xql, *xkh, *xkl, *xvh, *xvl, *wqh, *wkh, *wvh, *woh, *ch, *cl;
    cudaGetSymbolAddress((void**)&q, g_q);
    cudaGetSymbolAddress((void**)&k, g_k);
    cudaGetSymbolAddress((void**)&v, g_v);
    cudaGetSymbolAddress((void**)&xqh, g_xqh); cudaGetSymbolAddress((void**)&xql, g_xql);
    cudaGetSymbolAddress((void**)&xkh, g_xkh); cudaGetSymbolAddress((void**)&xkl, g_xkl);
    cudaGetSymbolAddress((void**)&xvh, g_xvh); cudaGetSymbolAddress((void**)&xvl, g_xvl);
    cudaGetSymbolAddress((void**)&wqh, g_wqh); cudaGetSymbolAddress((void**)&wkh, g_wkh);
    cudaGetSymbolAddress((void**)&wvh, g_wvh); cudaGetSymbolAddress((void**)&woh, g_woh);
    cudaGetSymbolAddress((void**)&ch, g_ch);   cudaGetSymbolAddress((void**)&cl, g_cl);

    cudaFuncSetAttribute(gemm_qkv,
                         cudaFuncAttributeMaxDynamicSharedMemorySize, GEMM_SMEM);
    cudaFuncSetAttribute(gemm_out,
                         cudaFuncAttributeMaxDynamicSharedMemorySize, GEMM_SMEM);
    cudaFuncSetAttribute(attn_mma,
                         cudaFuncAttributeMaxDynamicSharedMemorySize, ATTN_SMEM);

    const int n4x = S * DD / 4;       // 1M
    const int n4w = DD * DD / 4;      // 256K
    cvt_x<<<dim3((n4x + 255) / 256, 3), 256>>>(Xq, Xk, Xv,
                                               xqh, xql, xkh, xkl, xvh, xvl, n4x);
    cvt_w<<<dim3((n4w + 255) / 256, 4), 256>>>(Wq, Wk, Wv, Wo,
                                               wqh, wkh, wvh, woh, n4w);

    gemm_qkv<<<dim3(DD / 128, S / 128, 3), 256, GEMM_SMEM>>>(
        xqh, xql, xkh, xkl, xvh, xvl, wqh, wkh, wvh, bq, bk, bv, q, k, v, S);

    attn_mma<<<dim3(S / 128, HH), 256, ATTN_SMEM>>>(q, k, v, ch, cl, S);

    gemm_out<<<dim3(DD / 128, S / 128), 256, GEMM_SMEM>>>(ch, cl, woh, bo, out, S);
}